// round 9
// baseline (speedup 1.0000x reference)
#include <cuda_runtime.h>
#include <math.h>
#include <float.h>
#include <stdint.h>

#define BB 2048
#define FF 256
#define HH 1024
#define OO 256
#define TT 64

__device__ float    g_v [BB*HH];
__device__ float    g_i [BB*HH];
__device__ float    g_vo[BB*OO];
__device__ float    g_io[BB*OO];
__device__ float    g_m [BB*OO];
__device__ unsigned g_z [2][BB*(HH/32)];
__device__ unsigned g_xb[TT*BB*16];
__device__ __align__(16) float g_wAt[1536*HH];  // exact fp32, transposed [k][n]; k<512 in, else rec
__device__ __align__(16) float g_wBt[1024*OO];  // exact fp32, transposed [k][o]

#define CPA16(d, s) asm volatile("cp.async.ca.shared.global [%0], [%1], 16;" :: "r"(d), "l"(s))
#define CPCOMMIT()  asm volatile("cp.async.commit_group;" ::: "memory")
#define CPWAIT(n)   asm volatile("cp.async.wait_group %0;" :: "n"(n) : "memory")

__device__ __forceinline__ uint32_t smem_u32(const void* p) {
    uint32_t a;
    asm("{ .reg .u64 t; cvta.to.shared.u64 t, %1; cvt.u32.u64 %0, t; }" : "=r"(a) : "l"(p));
    return a;
}

// smem layout (bytes): sw[128][48] @0 (24576) | wbuf 2x64KB @24576 | zsh[512] @155648
#define WOFF 24576
#define ZOFF 155648
#define SMEMB 157696

__global__ void init_kernel() {
    int gid = blockIdx.x * 256 + threadIdx.x;
    if (gid < BB*HH) { g_v[gid] = 0.f; g_i[gid] = 0.f; }
    if (gid < BB*OO) { g_vo[gid] = 0.f; g_io[gid] = 0.f; g_m[gid] = -FLT_MAX; }
    if (gid < BB*(HH/32)) g_z[0][gid] = 0u;
}

__global__ void build_wAt(const float* __restrict__ w_in, const float* __restrict__ w_rec) {
    int n = blockIdx.x * 256 + threadIdx.x;  // 0..1023
    int k = blockIdx.y;                       // 0..1535
    g_wAt[k*HH + n] = (k < 512) ? w_in[n*512 + k] : w_rec[n*1024 + (k - 512)];
}
__global__ void build_wBt(const float* __restrict__ w_out) {
    int n = threadIdx.x;                      // 0..255
    int k = blockIdx.y;                       // 0..1023
    g_wBt[k*OO + n] = w_out[n*1024 + k];
}

// encoder — bitwise identical to R2
__global__ void enc_kernel(const float* __restrict__ x) {
    int gid = blockIdx.x * 256 + threadIdx.x;
    int b = gid >> 4, w = gid & 15;
    float sgn = (w < 8) ? 50.f : -50.f;
    int fbase = (w & 7) * 32;
    float c[32], v[32];
#pragma unroll
    for (int j = 0; j < 32; j++) { c[j] = fmaxf(__fmul_rn(sgn, x[b*FF + fbase + j]), 0.f); v[j] = 0.f; }
    unsigned* dst = g_xb + b*16 + w;
    for (int t = 0; t < TT; t++) {
        unsigned msk = 0u;
#pragma unroll
        for (int j = 0; j < 32; j++) {
            float d = __fadd_rn(c[j], -v[j]);
            v[j] = __fadd_rn(v[j], __fmul_rn(0.1f, d));
            if (v[j] > 1.0f) { msk |= (1u << j); v[j] = 0.f; }
        }
        dst[t * BB * 16] = msk;
    }
}

// grid=160: bid<128 roleA hidden step s (128b x 128h, gather K=1536);
//           bid>=128 roleB readout step s-1 (32 CTAs, 128b x 128o, gather K=1024).
__global__ void __launch_bounds__(256, 1) step_sp(int s) {
    extern __shared__ char smem[];
    const uint32_t sb = smem_u32(smem);
    unsigned* sw = (unsigned*)smem;
    float*    wb = (float*)(smem + WOFF);
    const int tid = threadIdx.x, lane = tid & 31, wid = tid >> 5;
    const bool roleA = blockIdx.x < 128;
    if (roleA && s >= TT) return;
    if (!roleA && s == 0) return;
    const int pr = s & 1;

    int b0, n0, nw, C;
    const float* wsrc; int wrow;
    if (roleA) {
        b0 = (blockIdx.x >> 3) * 128; n0 = (blockIdx.x & 7) * 128;
        nw = 48; C = 12; wsrc = g_wAt; wrow = HH;
    } else {
        int id = blockIdx.x - 128;
        b0 = (id >> 1) * 128; n0 = (id & 1) * 128;
        nw = 32; C = 8; wsrc = g_wBt; wrow = OO;
    }

    // ---- stage spike bit-words: sw[row][nw] ----
    for (int t = tid; t < 128 * nw; t += 256) {
        int row = t / nw, idx = t - row * nw;
        unsigned wv;
        if (roleA) {
            if (idx < 16) wv = g_xb[(s*BB + b0 + row)*16 + idx];
            else          wv = g_z[pr][(b0 + row)*32 + (idx - 16)];
        } else            wv = g_z[pr][(b0 + row)*32 + idx];
        sw[row * nw + idx] = wv;
    }

    // ---- weight chunk staging (cp.async, double buffer) ----
    auto stage = [&](int c) {
        int st = c & 1;
        int koff = roleA ? ((c < 4) ? c*128 : 512 + (c - 4)*128) : c*128;
#pragma unroll
        for (int j = 0; j < 16; j++) {
            int id = tid + j*256;           // 0..4095
            int krow = id >> 5, seg = id & 31;
            const float* src = wsrc + (size_t)(koff + krow)*wrow + n0 + seg*4;
            CPA16(sb + WOFF + (unsigned)(st*65536 + krow*512 + seg*16), src);
        }
        CPCOMMIT();
    };

    float accA[16][4], accB[16][4];
#pragma unroll
    for (int r = 0; r < 16; r++)
#pragma unroll
        for (int c = 0; c < 4; c++) { accA[r][c] = 0.f; accB[r][c] = 0.f; }

    const int rbase = wid * 16;
    const int lc4 = lane * 4;

    stage(0);
#pragma unroll 1
    for (int c = 0; c < C; c++) {
        if (c + 1 < C) { stage(c + 1); CPWAIT(1); } else { CPWAIT(0); }
        __syncthreads();
        const float* W = wb + (c & 1) * 16384;
        const bool phaseB = roleA && (c >= 4);
#pragma unroll
        for (int r = 0; r < 16; r++) {
            const unsigned* swr = sw + (rbase + r) * nw + c*4;
            float a0 = phaseB ? accB[r][0] : accA[r][0];
            float a1 = phaseB ? accB[r][1] : accA[r][1];
            float a2 = phaseB ? accB[r][2] : accA[r][2];
            float a3 = phaseB ? accB[r][3] : accA[r][3];
#pragma unroll
            for (int wl = 0; wl < 4; wl++) {
                unsigned wv = swr[wl];
                while (wv) {
                    int j = __ffs(wv) - 1;
                    wv &= wv - 1;
                    const float4 w4 = *(const float4*)&W[((wl*32 + j) << 7) + lc4];
                    a0 = __fadd_rn(a0, w4.x);
                    a1 = __fadd_rn(a1, w4.y);
                    a2 = __fadd_rn(a2, w4.z);
                    a3 = __fadd_rn(a3, w4.w);
                }
            }
            if (phaseB) { accB[r][0]=a0; accB[r][1]=a1; accB[r][2]=a2; accB[r][3]=a3; }
            else        { accA[r][0]=a0; accA[r][1]=a1; accA[r][2]=a2; accA[r][3]=a3; }
        }
        __syncthreads();
        if (roleA && c == 3) {
            // fold: accA = (i - 0.2*i) + accIn   (reference op order)
#pragma unroll
            for (int r = 0; r < 16; r++) {
                const int base = (b0 + rbase + r)*HH + n0 + lc4;
                float4 i4 = *(const float4*)&g_i[base];
                float ia[4] = {i4.x, i4.y, i4.z, i4.w};
#pragma unroll
                for (int cc = 0; cc < 4; cc++) {
                    float idc = __fsub_rn(ia[cc], __fmul_rn(0.2f, ia[cc]));
                    accA[r][cc] = __fadd_rn(idc, accA[r][cc]);
                }
            }
        }
    }

    if (roleA) {
        unsigned* zsh = (unsigned*)(smem + ZOFF);  // [128][4]
        for (int t = tid; t < 512; t += 256) zsh[t] = 0u;
        __syncthreads();
        const int wsel = lane >> 3, shf = (lane & 7) * 4;
#pragma unroll
        for (int r = 0; r < 16; r++) {
            const int rloc = rbase + r;
            const int base = (b0 + rloc)*HH + n0 + lc4;
            float4 i4 = *(const float4*)&g_i[base];
            float4 v4 = *(const float4*)&g_v[base];
            float ia[4] = {i4.x, i4.y, i4.z, i4.w};
            float va[4] = {v4.x, v4.y, v4.z, v4.w};
            unsigned nib = 0u;
#pragma unroll
            for (int cc = 0; cc < 4; cc++) {
                float d  = __fadd_rn(ia[cc], -va[cc]);
                float vd = __fadd_rn(va[cc], __fmul_rn(0.1f, d));
                bool  z  = vd > 1.0f;
                va[cc] = z ? 0.f : vd;
                ia[cc] = __fadd_rn(accA[r][cc], accB[r][cc]);   // (idc+accIn)+accRec
                if (z) nib |= (1u << cc);
            }
            *(float4*)&g_v[base] = make_float4(va[0], va[1], va[2], va[3]);
            *(float4*)&g_i[base] = make_float4(ia[0], ia[1], ia[2], ia[3]);
            if (nib) atomicOr(&zsh[rloc*4 + wsel], nib << shf);
        }
        __syncthreads();
        for (int t = tid; t < 512; t += 256) {
            int row = t >> 2, wd = t & 3;
            g_z[pr ^ 1][(b0 + row)*32 + (n0 >> 5) + wd] = zsh[t];
        }
    } else {
#pragma unroll
        for (int r = 0; r < 16; r++) {
            const int base = (b0 + rbase + r)*OO + n0 + lc4;
            float4 io4 = *(const float4*)&g_io[base];
            float4 vo4 = *(const float4*)&g_vo[base];
            float4 m4  = *(const float4*)&g_m [base];
            float ioa[4] = {io4.x, io4.y, io4.z, io4.w};
            float voa[4] = {vo4.x, vo4.y, vo4.z, vo4.w};
            float ma[4]  = {m4.x,  m4.y,  m4.z,  m4.w};
#pragma unroll
            for (int cc = 0; cc < 4; cc++) {
                float d   = __fadd_rn(ioa[cc], -voa[cc]);
                float von = __fadd_rn(voa[cc], __fmul_rn(0.1f, d));
                float idc = __fsub_rn(ioa[cc], __fmul_rn(0.2f, ioa[cc]));
                ioa[cc] = __fadd_rn(idc, accA[r][cc]);
                ma[cc]  = fmaxf(ma[cc], von);
                voa[cc] = von;
            }
            *(float4*)&g_vo[base] = make_float4(voa[0], voa[1], voa[2], voa[3]);
            *(float4*)&g_io[base] = make_float4(ioa[0], ioa[1], ioa[2], ioa[3]);
            *(float4*)&g_m [base] = make_float4(ma[0],  ma[1],  ma[2],  ma[3]);
        }
    }
}

__global__ void softmax_kernel(float* __restrict__ out) {
    __shared__ float red[256];
    int b = blockIdx.x, o = threadIdx.x;
    float v = g_m[b * OO + o];
    red[o] = v; __syncthreads();
    for (int st = 128; st > 0; st >>= 1) { if (o < st) red[o] = fmaxf(red[o], red[o + st]); __syncthreads(); }
    float mx = red[0]; __syncthreads();
    float e = expf(__fsub_rn(v, mx));
    red[o] = e; __syncthreads();
    for (int st = 128; st > 0; st >>= 1) { if (o < st) red[o] += red[o + st]; __syncthreads(); }
    out[b * OO + o] = e / red[0];
}

extern "C" void kernel_launch(void* const* d_in, const int* in_sizes, int n_in,
                              void* d_out, int out_size) {
    const float* x     = (const float*)d_in[0];
    const float* w_in  = (const float*)d_in[1];
    const float* w_rec = (const float*)d_in[2];
    const float* w_out = (const float*)d_in[3];
    float* out = (float*)d_out;

    cudaFuncSetAttribute(step_sp, cudaFuncAttributeMaxDynamicSharedMemorySize, SMEMB);

    init_kernel<<<(BB * HH + 255) / 256, 256>>>();
    build_wAt<<<dim3(4, 1536), 256>>>(w_in, w_rec);
    build_wBt<<<dim3(1, 1024), 256>>>(w_out);
    enc_kernel<<<BB * 16 / 256, 256>>>(x);
    for (int s = 0; s <= TT; s++)
        step_sp<<<160, 256, SMEMB>>>(s);
    softmax_kernel<<<BB, 256>>>(out);
}

// round 10
// speedup vs baseline: 1.2884x; 1.2884x over previous
#include <cuda_runtime.h>
#include <math.h>
#include <float.h>
#include <stdint.h>

#define BB 2048
#define FF 256
#define HH 1024
#define OO 256
#define TT 64

__device__ float    g_v [BB*HH];
__device__ float    g_i [BB*HH];
__device__ float    g_vo[BB*OO];
__device__ float    g_io[BB*OO];
__device__ float    g_m [BB*OO];
__device__ unsigned g_z [2][BB*(HH/32)];
__device__ unsigned g_xb[TT*BB*16];
__device__ __align__(16) float g_wAt[1536*HH];  // exact fp32, transposed [k][n]; k<512 in, else rec
__device__ __align__(16) float g_wBt[1024*OO];  // exact fp32, transposed [k][o]

#define CPA16(d, s) asm volatile("cp.async.ca.shared.global [%0], [%1], 16;" :: "r"(d), "l"(s))
#define CPCOMMIT()  asm volatile("cp.async.commit_group;" ::: "memory")
#define CPWAIT(n)   asm volatile("cp.async.wait_group %0;" :: "n"(n) : "memory")

__device__ __forceinline__ uint32_t smem_u32(const void* p) {
    uint32_t a;
    asm("{ .reg .u64 t; cvta.to.shared.u64 t, %1; cvt.u32.u64 %0, t; }" : "=r"(a) : "l"(p));
    return a;
}
// packed f32x2 FMA: both halves round .rn independently == scalar FFMA bitwise
#define FMA2(acc, a, b) \
    asm("fma.rn.f32x2 %0, %1, %2, %0;" : "+l"(acc) : "l"(a), "l"(b))
__device__ __forceinline__ uint64_t pk2(float x, float y) {
    uint64_t r;
    asm("mov.b64 %0, {%1, %2};" : "=l"(r) : "r"(__float_as_uint(x)), "r"(__float_as_uint(y)));
    return r;
}
__device__ __forceinline__ void upk(uint64_t p, float& lo, float& hi) {
    unsigned a, b;
    asm("mov.b64 {%0, %1}, %2;" : "=r"(a), "=r"(b) : "l"(p));
    lo = __uint_as_float(a); hi = __uint_as_float(b);
}

// smem layout (bytes): sw 128*48*4 @0 | aT 2*32*128*4 @24576 | wT 2*32*128*4 @57344 | zsh @90112
#define ATOFF 24576
#define WTOFF 57344
#define ZOFF  90112
#define SMEMB 122880   // padded > 113.5KB to force 1 CTA/SM

__global__ void init_kernel() {
    int gid = blockIdx.x * 256 + threadIdx.x;
    if (gid < BB*HH) { g_v[gid] = 0.f; g_i[gid] = 0.f; }
    if (gid < BB*OO) { g_vo[gid] = 0.f; g_io[gid] = 0.f; g_m[gid] = -FLT_MAX; }
    if (gid < BB*(HH/32)) g_z[0][gid] = 0u;
}

__global__ void build_wAt(const float* __restrict__ w_in, const float* __restrict__ w_rec) {
    int n = blockIdx.x * 256 + threadIdx.x;
    int k = blockIdx.y;
    g_wAt[k*HH + n] = (k < 512) ? w_in[n*512 + k] : w_rec[n*1024 + (k - 512)];
}
__global__ void build_wBt(const float* __restrict__ w_out) {
    int n = threadIdx.x;
    int k = blockIdx.y;
    g_wBt[k*OO + n] = w_out[n*1024 + k];
}

__global__ void enc_kernel(const float* __restrict__ x) {
    int gid = blockIdx.x * 256 + threadIdx.x;
    int b = gid >> 4, w = gid & 15;
    float sgn = (w < 8) ? 50.f : -50.f;
    int fbase = (w & 7) * 32;
    float c[32], v[32];
#pragma unroll
    for (int j = 0; j < 32; j++) { c[j] = fmaxf(__fmul_rn(sgn, x[b*FF + fbase + j]), 0.f); v[j] = 0.f; }
    unsigned* dst = g_xb + b*16 + w;
    for (int t = 0; t < TT; t++) {
        unsigned msk = 0u;
#pragma unroll
        for (int j = 0; j < 32; j++) {
            float d = __fadd_rn(c[j], -v[j]);
            v[j] = __fadd_rn(v[j], __fmul_rn(0.1f, d));
            if (v[j] > 1.0f) { msk |= (1u << j); v[j] = 0.f; }
        }
        dst[t * BB * 16] = msk;
    }
}

// grid=192: bid<128 roleA hidden step s (128x128, K=1536, FFMA2);
//           bid>=128 roleB readout step s-1 (64 CTAs, 128x64, K=1024).
__global__ void __launch_bounds__(256, 1) step_f2(int s) {
    extern __shared__ char smem[];
    const uint32_t sb = smem_u32(smem);
    unsigned* sw  = (unsigned*)smem;
    unsigned* zsh = (unsigned*)(smem + ZOFF);
    const int tid = threadIdx.x;
    const bool roleA = blockIdx.x < 128;
    if (roleA && s >= TT) return;
    if (!roleA && s == 0) return;
    const int pr = s & 1;

    int b0, n0, C, nwords;
    if (roleA) { b0 = (blockIdx.x >> 3) * 128; n0 = (blockIdx.x & 7) * 128; C = 48; nwords = 48; }
    else { int id = blockIdx.x - 128; b0 = (id >> 2) * 128; n0 = (id & 3) * 64; C = 32; nwords = 32; }

    const int tidy = tid >> 4;   // 0..15: rows tidy*8..+7
    const int tidx = tid & 15;   // 0..15: cols tidx*8 (roleA) / tidx*4 (roleB)

    // ---- prologue: stage spike words (stride 48 both roles), zero zsh ----
    for (int t = tid; t < 128 * nwords; t += 256) {
        int row = t / nwords, idx = t - row * nwords;
        unsigned wv;
        if (roleA) {
            if (idx < 16) wv = g_xb[(s*BB + b0 + row)*16 + idx];
            else          wv = g_z[pr][(b0 + row)*32 + (idx - 16)];
        } else            wv = g_z[pr][(b0 + row)*32 + idx];
        sw[row * 48 + idx] = wv;
    }
    if (roleA) for (int t = tid; t < 512; t += 256) zsh[t] = 0u;

    auto stage_w = [&](int c) {
        int st = c & 1;
        if (roleA) {
            int koff = (c < 16) ? c*32 : 512 + (c - 16)*32;
#pragma unroll
            for (int q = 0; q < 4; q++) {
                int id = tid + q*256;
                int j = id >> 5, seg = id & 31;
                const float* src = g_wAt + (size_t)(koff + j)*HH + n0 + seg*4;
                CPA16(sb + WTOFF + (unsigned)(st*16384 + j*512 + seg*16), src);
            }
        } else {
#pragma unroll
            for (int q = 0; q < 2; q++) {
                int id = tid + q*256;
                int j = id >> 4, seg = id & 15;
                const float* src = g_wBt + (size_t)(c*32 + j)*OO + n0 + seg*4;
                CPA16(sb + WTOFF + (unsigned)(st*16384 + j*512 + seg*16), src);
            }
        }
        CPCOMMIT();
    };

    auto expand_a = [&](int c, int st) {
        int j = tid >> 3, rs = (tid & 7) * 16;
        float f[16];
#pragma unroll
        for (int r = 0; r < 16; r++) {
            unsigned wv = sw[(rs + r)*48 + c];
            f[r] = ((wv >> j) & 1u) ? 1.0f : 0.0f;
        }
        float* dst = (float*)(smem + ATOFF) + st*4096 + j*128 + rs;
#pragma unroll
        for (int q = 0; q < 4; q++)
            *(float4*)(dst + q*4) = make_float4(f[q*4], f[q*4+1], f[q*4+2], f[q*4+3]);
    };

    stage_w(0);
    __syncthreads();      // sw visible to expand
    expand_a(0, 0);

    uint64_t acc[8][4];
#pragma unroll
    for (int u = 0; u < 8; u++)
#pragma unroll
        for (int p = 0; p < 4; p++) acc[u][p] = 0ull;

#pragma unroll 1
    for (int c = 0; c < C; c++) {
        const int st = c & 1;
        CPWAIT(0);
        __syncthreads();  // wT[st] + aT[st] ready; fold atomics (c==16) drained
        if (roleA && c == 16) {
            for (int t = tid; t < 512; t += 256) {
                int row = t >> 2, wd = t & 3;
                g_z[pr ^ 1][(b0 + row)*32 + (n0 >> 5) + wd] = zsh[t];
            }
        }
        if (c + 1 < C) stage_w(c + 1);

        const float* At = (const float*)(smem + ATOFF) + st*4096;
        const float* Wt = (const float*)(smem + WTOFF) + st*4096;
        if (roleA) {
#pragma unroll 8
            for (int j = 0; j < 32; j++) {
                float4 a4a = *(const float4*)(At + j*128 + tidy*8);
                float4 a4b = *(const float4*)(At + j*128 + tidy*8 + 4);
                float4 w4a = *(const float4*)(Wt + j*128 + tidx*8);
                float4 w4b = *(const float4*)(Wt + j*128 + tidx*8 + 4);
                uint64_t wp0 = pk2(w4a.x, w4a.y), wp1 = pk2(w4a.z, w4a.w);
                uint64_t wp2 = pk2(w4b.x, w4b.y), wp3 = pk2(w4b.z, w4b.w);
                float ar[8] = {a4a.x, a4a.y, a4a.z, a4a.w, a4b.x, a4b.y, a4b.z, a4b.w};
#pragma unroll
                for (int u = 0; u < 8; u++) {
                    uint64_t ad = pk2(ar[u], ar[u]);
                    FMA2(acc[u][0], ad, wp0);
                    FMA2(acc[u][1], ad, wp1);
                    FMA2(acc[u][2], ad, wp2);
                    FMA2(acc[u][3], ad, wp3);
                }
            }
        } else {
#pragma unroll 8
            for (int j = 0; j < 32; j++) {
                float4 a4a = *(const float4*)(At + j*128 + tidy*8);
                float4 a4b = *(const float4*)(At + j*128 + tidy*8 + 4);
                float4 w4  = *(const float4*)(Wt + j*128 + tidx*4);
                uint64_t wp0 = pk2(w4.x, w4.y), wp1 = pk2(w4.z, w4.w);
                float ar[8] = {a4a.x, a4a.y, a4a.z, a4a.w, a4b.x, a4b.y, a4b.z, a4b.w};
#pragma unroll
                for (int u = 0; u < 8; u++) {
                    uint64_t ad = pk2(ar[u], ar[u]);
                    FMA2(acc[u][0], ad, wp0);
                    FMA2(acc[u][1], ad, wp1);
                }
            }
        }
        if (c + 1 < C) expand_a(c + 1, st ^ 1);

        if (roleA && c == 15) {
            // fold: v/z update (old state) + g_i := (i - 0.2i) + accIn; reset acc
            const int colb = n0 + tidx*8;
            const int wsel = tidx >> 2, shf = (tidx & 3) * 8;
#pragma unroll
            for (int u = 0; u < 8; u++) {
                const int rloc = tidy*8 + u;
                const int base = (b0 + rloc)*HH + colb;
                float4 i4a = *(const float4*)&g_i[base], i4b = *(const float4*)&g_i[base+4];
                float4 v4a = *(const float4*)&g_v[base], v4b = *(const float4*)&g_v[base+4];
                float iv[8] = {i4a.x, i4a.y, i4a.z, i4a.w, i4b.x, i4b.y, i4b.z, i4b.w};
                float vv[8] = {v4a.x, v4a.y, v4a.z, v4a.w, v4b.x, v4b.y, v4b.z, v4b.w};
                float aIn[8];
#pragma unroll
                for (int p = 0; p < 4; p++) { upk(acc[u][p], aIn[p*2], aIn[p*2+1]); acc[u][p] = 0ull; }
                float vn[8], fo[8];
                unsigned bits = 0;
#pragma unroll
                for (int cc = 0; cc < 8; cc++) {
                    float d   = __fadd_rn(iv[cc], -vv[cc]);
                    float vd  = __fadd_rn(vv[cc], __fmul_rn(0.1f, d));
                    float idc = __fsub_rn(iv[cc], __fmul_rn(0.2f, iv[cc]));
                    bool  z   = vd > 1.0f;
                    vn[cc] = z ? 0.f : vd;
                    fo[cc] = __fadd_rn(idc, aIn[cc]);
                    if (z) bits |= (1u << cc);
                }
                *(float4*)&g_v[base]   = make_float4(vn[0], vn[1], vn[2], vn[3]);
                *(float4*)&g_v[base+4] = make_float4(vn[4], vn[5], vn[6], vn[7]);
                *(float4*)&g_i[base]   = make_float4(fo[0], fo[1], fo[2], fo[3]);
                *(float4*)&g_i[base+4] = make_float4(fo[4], fo[5], fo[6], fo[7]);
                if (bits) atomicOr(&zsh[rloc*4 + wsel], bits << shf);
            }
        }
    }

    if (roleA) {
        // epilogue: i_new = folded + accRec
        const int colb = n0 + tidx*8;
#pragma unroll
        for (int u = 0; u < 8; u++) {
            const int base = (b0 + tidy*8 + u)*HH + colb;
            float4 f4a = *(const float4*)&g_i[base], f4b = *(const float4*)&g_i[base+4];
            float fo[8] = {f4a.x, f4a.y, f4a.z, f4a.w, f4b.x, f4b.y, f4b.z, f4b.w};
            float rc[8];
#pragma unroll
            for (int p = 0; p < 4; p++) upk(acc[u][p], rc[p*2], rc[p*2+1]);
            float nw[8];
#pragma unroll
            for (int cc = 0; cc < 8; cc++) nw[cc] = __fadd_rn(fo[cc], rc[cc]);
            *(float4*)&g_i[base]   = make_float4(nw[0], nw[1], nw[2], nw[3]);
            *(float4*)&g_i[base+4] = make_float4(nw[4], nw[5], nw[6], nw[7]);
        }
    } else {
        const int colb = n0 + tidx*4;
#pragma unroll
        for (int u = 0; u < 8; u++) {
            const int base = (b0 + tidy*8 + u)*OO + colb;
            float4 io4 = *(const float4*)&g_io[base];
            float4 vo4 = *(const float4*)&g_vo[base];
            float4 m4  = *(const float4*)&g_m [base];
            float ioa[4] = {io4.x, io4.y, io4.z, io4.w};
            float voa[4] = {vo4.x, vo4.y, vo4.z, vo4.w};
            float ma[4]  = {m4.x,  m4.y,  m4.z,  m4.w};
            float av[4];
            upk(acc[u][0], av[0], av[1]);
            upk(acc[u][1], av[2], av[3]);
#pragma unroll
            for (int cc = 0; cc < 4; cc++) {
                float d   = __fadd_rn(ioa[cc], -voa[cc]);
                float von = __fadd_rn(voa[cc], __fmul_rn(0.1f, d));
                float idc = __fsub_rn(ioa[cc], __fmul_rn(0.2f, ioa[cc]));
                ioa[cc] = __fadd_rn(idc, av[cc]);
                ma[cc]  = fmaxf(ma[cc], von);
                voa[cc] = von;
            }
            *(float4*)&g_vo[base] = make_float4(voa[0], voa[1], voa[2], voa[3]);
            *(float4*)&g_io[base] = make_float4(ioa[0], ioa[1], ioa[2], ioa[3]);
            *(float4*)&g_m [base] = make_float4(ma[0],  ma[1],  ma[2],  ma[3]);
        }
    }
}

__global__ void softmax_kernel(float* __restrict__ out) {
    __shared__ float red[256];
    int b = blockIdx.x, o = threadIdx.x;
    float v = g_m[b * OO + o];
    red[o] = v; __syncthreads();
    for (int st = 128; st > 0; st >>= 1) { if (o < st) red[o] = fmaxf(red[o], red[o + st]); __syncthreads(); }
    float mx = red[0]; __syncthreads();
    float e = expf(__fsub_rn(v, mx));
    red[o] = e; __syncthreads();
    for (int st = 128; st > 0; st >>= 1) { if (o < st) red[o] += red[o + st]; __syncthreads(); }
    out[b * OO + o] = e / red[0];
}

extern "C" void kernel_launch(void* const* d_in, const int* in_sizes, int n_in,
                              void* d_out, int out_size) {
    const float* x     = (const float*)d_in[0];
    const float* w_in  = (const float*)d_in[1];
    const float* w_rec = (const float*)d_in[2];
    const float* w_out = (const float*)d_in[3];
    float* out = (float*)d_out;

    cudaFuncSetAttribute(step_f2, cudaFuncAttributeMaxDynamicSharedMemorySize, SMEMB);

    init_kernel<<<(BB * HH + 255) / 256, 256>>>();
    build_wAt<<<dim3(4, 1536), 256>>>(w_in, w_rec);
    build_wBt<<<dim3(1, 1024), 256>>>(w_out);
    enc_kernel<<<BB * 16 / 256, 256>>>(x);
    for (int s = 0; s <= TT; s++)
        step_f2<<<192, 256, SMEMB>>>(s);
    softmax_kernel<<<BB, 256>>>(out);
}

// round 11
// speedup vs baseline: 1.3631x; 1.0580x over previous
#include <cuda_runtime.h>
#include <math.h>
#include <float.h>
#include <stdint.h>

#define BB 2048
#define FF 256
#define HH 1024
#define OO 256
#define TT 64

__device__ float    g_v [BB*HH];
__device__ float    g_i [BB*HH];
__device__ float    g_vo[BB*OO];
__device__ float    g_io[BB*OO];
__device__ float    g_m [BB*OO];
__device__ unsigned g_z [2][BB*(HH/32)];
__device__ unsigned g_xb[TT*BB*16];
__device__ __align__(16) float g_wAt[1536*HH];  // exact fp32, transposed [k][n]
__device__ __align__(16) float g_wBt[1024*OO];  // exact fp32, transposed [k][o]

#define CPA16(d, s) asm volatile("cp.async.ca.shared.global [%0], [%1], 16;" :: "r"(d), "l"(s))
#define CPCOMMIT()  asm volatile("cp.async.commit_group;" ::: "memory")
#define CPWAIT(n)   asm volatile("cp.async.wait_group %0;" :: "n"(n) : "memory")

__device__ __forceinline__ uint32_t smem_u32(const void* p) {
    uint32_t a;
    asm("{ .reg .u64 t; cvta.to.shared.u64 t, %1; cvt.u32.u64 %0, t; }" : "=r"(a) : "l"(p));
    return a;
}
// packed f32x2 ops: each half rounds .rn independently == scalar bitwise
#define FMA2(acc, a, b) asm("fma.rn.f32x2 %0, %1, %2, %0;" : "+l"(acc) : "l"(a), "l"(b))
#define ADD2(acc, b)    asm("add.rn.f32x2 %0, %0, %1;"     : "+l"(acc) : "l"(b))
__device__ __forceinline__ uint64_t pk2(float x, float y) {
    uint64_t r;
    asm("mov.b64 %0, {%1, %2};" : "=l"(r) : "r"(__float_as_uint(x)), "r"(__float_as_uint(y)));
    return r;
}
__device__ __forceinline__ void upk(uint64_t p, float& lo, float& hi) {
    unsigned a, b;
    asm("mov.b64 {%0, %1}, %2;" : "=r"(a), "=r"(b) : "l"(p));
    lo = __uint_as_float(a); hi = __uint_as_float(b);
}

// smem: sw 128*48*4 @0 | aT 2*32*128*4 @24576 | wT 2*32*128*4 @57344 | zsh @90112
#define ATOFF 24576
#define WTOFF 57344
#define ZOFF  90112
#define SMEMB 92160

__global__ void init_kernel() {
    int gid = blockIdx.x * 256 + threadIdx.x;
    if (gid < BB*HH) { g_v[gid] = 0.f; g_i[gid] = 0.f; }
    if (gid < BB*OO) { g_vo[gid] = 0.f; g_io[gid] = 0.f; g_m[gid] = -FLT_MAX; }
    if (gid < BB*(HH/32)) g_z[0][gid] = 0u;
}

__global__ void build_wAt(const float* __restrict__ w_in, const float* __restrict__ w_rec) {
    int n = blockIdx.x * 256 + threadIdx.x;
    int k = blockIdx.y;
    g_wAt[k*HH + n] = (k < 512) ? w_in[n*512 + k] : w_rec[n*1024 + (k - 512)];
}
__global__ void build_wBt(const float* __restrict__ w_out) {
    int n = threadIdx.x;
    int k = blockIdx.y;
    g_wBt[k*OO + n] = w_out[n*1024 + k];
}

__global__ void enc_kernel(const float* __restrict__ x) {
    int gid = blockIdx.x * 256 + threadIdx.x;
    int b = gid >> 4, w = gid & 15;
    float sgn = (w < 8) ? 50.f : -50.f;
    int fbase = (w & 7) * 32;
    float c[32], v[32];
#pragma unroll
    for (int j = 0; j < 32; j++) { c[j] = fmaxf(__fmul_rn(sgn, x[b*FF + fbase + j]), 0.f); v[j] = 0.f; }
    unsigned* dst = g_xb + b*16 + w;
    for (int t = 0; t < TT; t++) {
        unsigned msk = 0u;
#pragma unroll
        for (int j = 0; j < 32; j++) {
            float d = __fadd_rn(c[j], -v[j]);
            v[j] = __fadd_rn(v[j], __fmul_rn(0.1f, d));
            if (v[j] > 1.0f) { msk |= (1u << j); v[j] = 0.f; }
        }
        dst[t * BB * 16] = msk;
    }
}

// grid=128, single wave. Each CTA: hidden tile (128b x 128h, K=1536, FFMA2) for
// step s (if s<TT), then readout slice (16b x 256o, K=1024, sparse ADD2) for
// step s-1 (if s>=1). CTA (bt=bid>>3, nt=bid&7): hidden rows b0=bt*128, cols
// n0=nt*128; readout rows b0+nt*16..+15 (z-words already in smem).
__global__ void __launch_bounds__(256, 1) step_f2(int s) {
    extern __shared__ char smem[];
    const uint32_t sb = smem_u32(smem);
    unsigned* sw  = (unsigned*)smem;
    unsigned* zsh = (unsigned*)(smem + ZOFF);
    const int tid = threadIdx.x, bid = blockIdx.x;
    const int pr = s & 1;
    const int b0 = (bid >> 3) * 128;
    const int n0 = (bid & 7) * 128;
    const int tidy = tid >> 4, tidx = tid & 15;

    // ---- prologue: stage spike words sw[row][48] (xb 0..15 | z 16..47) ----
    for (int t = tid; t < 128 * 48; t += 256) {
        int row = t / 48, idx = t - row * 48;
        unsigned wv;
        if (idx < 16) wv = (s < TT) ? g_xb[(s*BB + b0 + row)*16 + idx] : 0u;
        else          wv = g_z[pr][(b0 + row)*32 + (idx - 16)];
        sw[row * 48 + idx] = wv;
    }

    if (s < TT) {
        for (int t = tid; t < 512; t += 256) zsh[t] = 0u;

        auto stage_w = [&](int c) {
            int st = c & 1;
            int koff = (c < 16) ? c*32 : 512 + (c - 16)*32;
#pragma unroll
            for (int q = 0; q < 4; q++) {
                int id = tid + q*256;
                int j = id >> 5, seg = id & 31;
                const float* src = g_wAt + (size_t)(koff + j)*HH + n0 + seg*4;
                CPA16(sb + WTOFF + (unsigned)(st*16384 + j*512 + seg*16), src);
            }
            CPCOMMIT();
        };
        auto expand_a = [&](int c, int st) {
            int j = tid >> 3, rs = (tid & 7) * 16;
            float f[16];
#pragma unroll
            for (int r = 0; r < 16; r++) {
                unsigned wv = sw[(rs + r)*48 + c];
                f[r] = ((wv >> j) & 1u) ? 1.0f : 0.0f;
            }
            float* dst = (float*)(smem + ATOFF) + st*4096 + j*128 + rs;
#pragma unroll
            for (int q = 0; q < 4; q++)
                *(float4*)(dst + q*4) = make_float4(f[q*4], f[q*4+1], f[q*4+2], f[q*4+3]);
        };

        stage_w(0);
        __syncthreads();
        expand_a(0, 0);

        uint64_t acc[8][4];
#pragma unroll
        for (int u = 0; u < 8; u++)
#pragma unroll
            for (int p = 0; p < 4; p++) acc[u][p] = 0ull;

#pragma unroll 1
        for (int c = 0; c < 48; c++) {
            const int st = c & 1;
            CPWAIT(0);
            __syncthreads();
            if (c == 16) {
                for (int t = tid; t < 512; t += 256) {
                    int row = t >> 2, wd = t & 3;
                    g_z[pr ^ 1][(b0 + row)*32 + (n0 >> 5) + wd] = zsh[t];
                }
            }
            if (c + 1 < 48) stage_w(c + 1);

            const float* At = (const float*)(smem + ATOFF) + st*4096;
            const float* Wt = (const float*)(smem + WTOFF) + st*4096;
#pragma unroll 8
            for (int j = 0; j < 32; j++) {
                float4 a4a = *(const float4*)(At + j*128 + tidy*8);
                float4 a4b = *(const float4*)(At + j*128 + tidy*8 + 4);
                float4 w4a = *(const float4*)(Wt + j*128 + tidx*8);
                float4 w4b = *(const float4*)(Wt + j*128 + tidx*8 + 4);
                uint64_t wp0 = pk2(w4a.x, w4a.y), wp1 = pk2(w4a.z, w4a.w);
                uint64_t wp2 = pk2(w4b.x, w4b.y), wp3 = pk2(w4b.z, w4b.w);
                float ar[8] = {a4a.x, a4a.y, a4a.z, a4a.w, a4b.x, a4b.y, a4b.z, a4b.w};
#pragma unroll
                for (int u = 0; u < 8; u++) {
                    uint64_t ad = pk2(ar[u], ar[u]);
                    FMA2(acc[u][0], ad, wp0);
                    FMA2(acc[u][1], ad, wp1);
                    FMA2(acc[u][2], ad, wp2);
                    FMA2(acc[u][3], ad, wp3);
                }
            }
            if (c + 1 < 48) expand_a(c + 1, st ^ 1);

            if (c == 15) {
                // fold: v/z update (old state) + g_i := (i - 0.2i) + accIn
                const int colb = n0 + tidx*8;
                const int wsel = tidx >> 2, shf = (tidx & 3) * 8;
#pragma unroll
                for (int u = 0; u < 8; u++) {
                    const int rloc = tidy*8 + u;
                    const int base = (b0 + rloc)*HH + colb;
                    float4 i4a = *(const float4*)&g_i[base], i4b = *(const float4*)&g_i[base+4];
                    float4 v4a = *(const float4*)&g_v[base], v4b = *(const float4*)&g_v[base+4];
                    float iv[8] = {i4a.x, i4a.y, i4a.z, i4a.w, i4b.x, i4b.y, i4b.z, i4b.w};
                    float vv[8] = {v4a.x, v4a.y, v4a.z, v4a.w, v4b.x, v4b.y, v4b.z, v4b.w};
                    float aIn[8];
#pragma unroll
                    for (int p = 0; p < 4; p++) { upk(acc[u][p], aIn[p*2], aIn[p*2+1]); acc[u][p] = 0ull; }
                    float vn[8], fo[8];
                    unsigned bits = 0;
#pragma unroll
                    for (int cc = 0; cc < 8; cc++) {
                        float d   = __fadd_rn(iv[cc], -vv[cc]);
                        float vd  = __fadd_rn(vv[cc], __fmul_rn(0.1f, d));
                        float idc = __fsub_rn(iv[cc], __fmul_rn(0.2f, iv[cc]));
                        bool  z   = vd > 1.0f;
                        vn[cc] = z ? 0.f : vd;
                        fo[cc] = __fadd_rn(idc, aIn[cc]);
                        if (z) bits |= (1u << cc);
                    }
                    *(float4*)&g_v[base]   = make_float4(vn[0], vn[1], vn[2], vn[3]);
                    *(float4*)&g_v[base+4] = make_float4(vn[4], vn[5], vn[6], vn[7]);
                    *(float4*)&g_i[base]   = make_float4(fo[0], fo[1], fo[2], fo[3]);
                    *(float4*)&g_i[base+4] = make_float4(fo[4], fo[5], fo[6], fo[7]);
                    if (bits) atomicOr(&zsh[rloc*4 + wsel], bits << shf);
                }
            }
        }

        // epilogue: i_new = folded + accRec
        const int colb = n0 + tidx*8;
#pragma unroll
        for (int u = 0; u < 8; u++) {
            const int base = (b0 + tidy*8 + u)*HH + colb;
            float4 f4a = *(const float4*)&g_i[base], f4b = *(const float4*)&g_i[base+4];
            float fo[8] = {f4a.x, f4a.y, f4a.z, f4a.w, f4b.x, f4b.y, f4b.z, f4b.w};
            float rc[8];
#pragma unroll
            for (int p = 0; p < 4; p++) upk(acc[u][p], rc[p*2], rc[p*2+1]);
            float nw[8];
#pragma unroll
            for (int cc = 0; cc < 8; cc++) nw[cc] = __fadd_rn(fo[cc], rc[cc]);
            *(float4*)&g_i[base]   = make_float4(nw[0], nw[1], nw[2], nw[3]);
            *(float4*)&g_i[base+4] = make_float4(nw[4], nw[5], nw[6], nw[7]);
        }
    }

    // ---------------- readout phase (step s-1) ----------------
    if (s >= 1) {
        __syncthreads();   // sw visible (s==TT path) / wT free (mainloop done)
        const int rloc = (bid & 7)*16 + (tid >> 4);   // row-local index in sw
        const int c0 = (tid & 15) * 4;                // col base; groups at +64
        uint64_t ro[8];
#pragma unroll
        for (int p = 0; p < 8; p++) ro[p] = 0ull;

        auto stage_o = [&](int ch) {
            int st = ch & 1;
#pragma unroll
            for (int q = 0; q < 4; q++) {
                int id = tid + q*256;
                int j = id >> 6, seg = id & 63;
                const float* src = g_wBt + (size_t)(ch*16 + j)*OO + seg*4;
                CPA16(sb + WTOFF + (unsigned)(st*16384 + j*1024 + seg*16), src);
            }
            CPCOMMIT();
        };
        stage_o(0);
        const unsigned* zrow = sw + rloc*48 + 16;
#pragma unroll 1
        for (int ch = 0; ch < 64; ch++) {
            CPWAIT(0);
            __syncthreads();
            if (ch + 1 < 64) stage_o(ch + 1);
            const float* Wo = (const float*)(smem + WTOFF) + (ch & 1)*4096;
            unsigned zw = zrow[ch >> 1];
            int bb = (ch & 1) * 16;
#pragma unroll
            for (int j = 0; j < 16; j++) {
                if ((zw >> (bb + j)) & 1u) {   // skip +0 terms: bit-exact (R9-proven)
                    const float* wr = Wo + j*256 + c0;
                    float4 w0 = *(const float4*)(wr);
                    float4 w1 = *(const float4*)(wr + 64);
                    float4 w2 = *(const float4*)(wr + 128);
                    float4 w3 = *(const float4*)(wr + 192);
                    ADD2(ro[0], pk2(w0.x, w0.y)); ADD2(ro[1], pk2(w0.z, w0.w));
                    ADD2(ro[2], pk2(w1.x, w1.y)); ADD2(ro[3], pk2(w1.z, w1.w));
                    ADD2(ro[4], pk2(w2.x, w2.y)); ADD2(ro[5], pk2(w2.z, w2.w));
                    ADD2(ro[6], pk2(w3.x, w3.y)); ADD2(ro[7], pk2(w3.z, w3.w));
                }
            }
        }

        const int rg = b0 + rloc;
#pragma unroll
        for (int p = 0; p < 4; p++) {
            const int base = rg*OO + c0 + p*64;
            float4 io4 = *(const float4*)&g_io[base];
            float4 vo4 = *(const float4*)&g_vo[base];
            float4 m4  = *(const float4*)&g_m [base];
            float ioa[4] = {io4.x, io4.y, io4.z, io4.w};
            float voa[4] = {vo4.x, vo4.y, vo4.z, vo4.w};
            float ma[4]  = {m4.x,  m4.y,  m4.z,  m4.w};
            float av[4];
            upk(ro[p*2],     av[0], av[1]);
            upk(ro[p*2 + 1], av[2], av[3]);
#pragma unroll
            for (int cc = 0; cc < 4; cc++) {
                float d   = __fadd_rn(ioa[cc], -voa[cc]);
                float von = __fadd_rn(voa[cc], __fmul_rn(0.1f, d));
                float idc = __fsub_rn(ioa[cc], __fmul_rn(0.2f, ioa[cc]));
                ioa[cc] = __fadd_rn(idc, av[cc]);
                ma[cc]  = fmaxf(ma[cc], von);
                voa[cc] = von;
            }
            *(float4*)&g_vo[base] = make_float4(voa[0], voa[1], voa[2], voa[3]);
            *(float4*)&g_io[base] = make_float4(ioa[0], ioa[1], ioa[2], ioa[3]);
            *(float4*)&g_m [base] = make_float4(ma[0],  ma[1],  ma[2],  ma[3]);
        }
    }
}

__global__ void softmax_kernel(float* __restrict__ out) {
    __shared__ float red[256];
    int b = blockIdx.x, o = threadIdx.x;
    float v = g_m[b * OO + o];
    red[o] = v; __syncthreads();
    for (int st = 128; st > 0; st >>= 1) { if (o < st) red[o] = fmaxf(red[o], red[o + st]); __syncthreads(); }
    float mx = red[0]; __syncthreads();
    float e = expf(__fsub_rn(v, mx));
    red[o] = e; __syncthreads();
    for (int st = 128; st > 0; st >>= 1) { if (o < st) red[o] += red[o + st]; __syncthreads(); }
    out[b * OO + o] = e / red[0];
}

extern "C" void kernel_launch(void* const* d_in, const int* in_sizes, int n_in,
                              void* d_out, int out_size) {
    const float* x     = (const float*)d_in[0];
    const float* w_in  = (const float*)d_in[1];
    const float* w_rec = (const float*)d_in[2];
    const float* w_out = (const float*)d_in[3];
    float* out = (float*)d_out;

    cudaFuncSetAttribute(step_f2, cudaFuncAttributeMaxDynamicSharedMemorySize, SMEMB);

    init_kernel<<<(BB * HH + 255) / 256, 256>>>();
    build_wAt<<<dim3(4, 1536), 256>>>(w_in, w_rec);
    build_wBt<<<dim3(1, 1024), 256>>>(w_out);
    enc_kernel<<<BB * 16 / 256, 256>>>(x);
    for (int s = 0; s <= TT; s++)
        step_f2<<<128, 256, SMEMB>>>(s);
    softmax_kernel<<<BB, 256>>>(out);
}